// round 1
// baseline (speedup 1.0000x reference)
#include <cuda_runtime.h>
#include <math.h>

#define NN 512
#define BIT 64
#define NCLS 100
#define ALPHA 5.0f
#define LAM 1.0f

// Scratch (allocation-free: __device__ globals)
__device__ float g_ip[NN * NN];
__device__ int   g_lbl[NN];
__device__ float g_rowloss[NN];
__device__ int   g_valid[NN];

// -------------------------------------------------------------------------
// Kernel 1: recover integer labels from one-hot y [N, NCLS]
// -------------------------------------------------------------------------
__global__ void labels_kernel(const float* __restrict__ y) {
    int i = blockIdx.x * blockDim.x + threadIdx.x;
    if (i < NN) {
        const float* row = y + (size_t)i * NCLS;
        int lbl = 0;
        #pragma unroll 4
        for (int j = 0; j < NCLS; ++j) {
            if (row[j] > 0.5f) lbl = j;
        }
        g_lbl[i] = lbl;
    }
}

// -------------------------------------------------------------------------
// Kernel 2: ip = u @ u^T   (one block per row i; u[i] broadcast via smem,
// each thread j does a float4 dot with row j; u is L2-resident)
// -------------------------------------------------------------------------
__global__ void ip_kernel(const float* __restrict__ u) {
    __shared__ float4 ui[BIT / 4];
    int i = blockIdx.x;
    int j = threadIdx.x;
    if (j < BIT / 4) ui[j] = ((const float4*)(u + (size_t)i * BIT))[j];
    __syncthreads();

    const float4* __restrict__ uj = (const float4*)(u + (size_t)j * BIT);
    float acc = 0.0f;
    #pragma unroll
    for (int k = 0; k < BIT / 4; ++k) {
        float4 a = ui[k];
        float4 b = uj[k];
        acc += a.x * b.x + a.y * b.y + a.z * b.z + a.w * b.w;
    }
    g_ip[(size_t)i * NN + j] = acc;
}

// -------------------------------------------------------------------------
// Kernel 3: per-row masked triplet loss. One block per row r.
// Only (p in pos(r)) x (all n) pairs are evaluated; n filtered by neg mask.
// Fixed-order reduction -> deterministic.
// -------------------------------------------------------------------------
__global__ void row_loss_kernel() {
    __shared__ float ipr[NN];
    __shared__ unsigned char isneg[NN];
    __shared__ short poslist[NN];
    __shared__ int   s_npos;
    __shared__ float red[256];

    int r   = blockIdx.x;
    int tid = threadIdx.x;
    int lr  = g_lbl[r];

    for (int j = tid; j < NN; j += blockDim.x) {
        ipr[j]   = g_ip[(size_t)r * NN + j];
        isneg[j] = (g_lbl[j] != lr) ? 1 : 0;
    }
    __syncthreads();

    // Deterministic positive-index compaction (serial scan by thread 0;
    // 512 iterations, negligible).
    if (tid == 0) {
        int c = 0;
        for (int j = 0; j < NN; ++j) {
            if (!isneg[j]) poslist[c++] = (short)j;
        }
        s_npos = c;
    }
    __syncthreads();

    int npos = s_npos;
    int nneg = NN - npos;

    float acc = 0.0f;
    int total = npos * NN;
    for (int idx = tid; idx < total; idx += blockDim.x) {
        int p = poslist[idx >> 9];     // idx / 512
        int n = idx & (NN - 1);        // idx % 512
        if (isneg[n]) {
            float t = ipr[p] - ipr[n] - ALPHA;
            t = fminf(fmaxf(t, -100.0f), 50.0f);
            // f = log1p(exp(t)) - t  (clamp keeps exp finite, matches ref)
            acc += log1pf(expf(t)) - t;
        }
    }

    red[tid] = acc;
    __syncthreads();
    #pragma unroll
    for (int s = 128; s > 0; s >>= 1) {
        if (tid < s) red[tid] += red[tid + s];
        __syncthreads();
    }

    if (tid == 0) {
        float pair_count = fmaxf((float)(npos * nneg), 1.0f);
        g_rowloss[r] = red[0] / pair_count;
        g_valid[r]   = (npos > 0 && nneg > 0) ? 1 : 0;
    }
}

// -------------------------------------------------------------------------
// Kernel 4: final reduce (loss1) + quantization penalty (loss2), fused.
// Single block, fixed-order tree reduction -> deterministic scalar.
// -------------------------------------------------------------------------
__global__ void final_kernel(const float* __restrict__ u, float* __restrict__ out) {
    __shared__ float red1[256];
    __shared__ float red2[256];
    __shared__ int   redc[256];

    int tid = threadIdx.x;

    float s1 = 0.0f;
    int   cnt = 0;
    for (int r = tid; r < NN; r += 256) {
        if (g_valid[r]) { s1 += g_rowloss[r]; cnt++; }
    }

    float s2 = 0.0f;
    for (int i = tid; i < NN * BIT; i += 256) {
        float v  = u[i];
        float sg = (v > 0.0f) ? 1.0f : ((v < 0.0f) ? -1.0f : 0.0f);
        float d  = v - sg;
        s2 += d * d;
    }

    red1[tid] = s1;
    red2[tid] = s2;
    redc[tid] = cnt;
    __syncthreads();
    #pragma unroll
    for (int s = 128; s > 0; s >>= 1) {
        if (tid < s) {
            red1[tid] += red1[tid + s];
            red2[tid] += red2[tid + s];
            redc[tid] += redc[tid + s];
        }
        __syncthreads();
    }

    if (tid == 0) {
        float count = (float)redc[0];
        float loss1 = (count > 0.0f) ? (red1[0] / fmaxf(count, 1.0f)) : 0.0f;
        float loss2 = LAM * red2[0] / (float)(NN * BIT);
        out[0] = loss1 + loss2;
    }
}

// -------------------------------------------------------------------------
extern "C" void kernel_launch(void* const* d_in, const int* in_sizes, int n_in,
                              void* d_out, int out_size) {
    // Identify inputs by size: u is N*BIT=32768, y is N*NCLS=51200.
    const float* u;
    const float* y;
    if (in_sizes[0] == NN * BIT) {
        u = (const float*)d_in[0];
        y = (const float*)d_in[1];
    } else {
        u = (const float*)d_in[1];
        y = (const float*)d_in[0];
    }
    float* out = (float*)d_out;

    labels_kernel<<<1, NN>>>(y);
    ip_kernel<<<NN, NN>>>(u);
    row_loss_kernel<<<NN, 256>>>();
    final_kernel<<<1, 256>>>(u, out);
}

// round 4
// speedup vs baseline: 1.8509x; 1.8509x over previous
#include <cuda_runtime.h>
#include <math.h>

#define NN    512
#define BIT   64
#define NCLS  100
#define ALPHA 5.0f
#define LAM   1.0f
#define RPB   4                 // rows per block
#define NB    (NN / RPB)        // 128 blocks
#define NT    256               // threads per block

// Scratch (allocation-free: __device__ globals)
__device__ float g_rowloss[NN];
__device__ int   g_valid[NN];
__device__ float g_loss2[NB];

// ---------------------------------------------------------------------------
// Fused kernel: labels (implicit), ip rows, masked triplet loss, loss2 partial.
// One block handles RPB=4 anchor rows; streams all of u once per block.
// ---------------------------------------------------------------------------
__global__ void __launch_bounds__(NT) fused_kernel(const float* __restrict__ u,
                                                   const float* __restrict__ y) {
    __shared__ float4 s_ur[RPB][BIT / 4];          // anchor rows of u     (1 KB)
    __shared__ float  s_ip[RPB][NN];               // ip rows              (8 KB)
    __shared__ unsigned char s_isneg[RPB][NN];     // negative masks       (2 KB)
    __shared__ int    s_lbl[RPB];
    __shared__ unsigned long long s_mask[8];       // pos bitmask, 64 j's per slot
    __shared__ short  s_poslist[NN];               // worst-case safe      (1 KB)
    __shared__ int    s_npos;
    __shared__ float  s_red[NT];                   // reduction scratch    (1 KB)

    const int tid = threadIdx.x;
    const int r0  = blockIdx.x * RPB;

    if (tid < RPB) s_lbl[tid] = 0;

    // --- load anchor rows of u into smem (64 float4 loads) ---
    if (tid < RPB * (BIT / 4)) {
        int i = tid / (BIT / 4);
        int k = tid % (BIT / 4);
        s_ur[i][k] = ((const float4*)(u + (size_t)(r0 + i) * BIT))[k];
    }
    __syncthreads();

    // --- recover labels of the RPB anchor rows from one-hot y ---
    // FIX (R3 bug): RPB*NCLS = 400 > NT = 256, so must grid-stride, not guard.
    for (int t = tid; t < RPB * NCLS; t += NT) {
        int i = t / NCLS;
        int c = t % NCLS;
        if (y[(size_t)(r0 + i) * NCLS + c] > 0.5f) s_lbl[i] = c;
    }
    __syncthreads();

    int lbl0 = s_lbl[0], lbl1 = s_lbl[1], lbl2 = s_lbl[2], lbl3 = s_lbl[3];

    // --- stream all 512 rows of u once; 4 dot products each; isneg via y ---
    for (int j = tid; j < NN; j += NT) {
        const float4* __restrict__ uj = (const float4*)(u + (size_t)j * BIT);
        float a0 = 0.f, a1 = 0.f, a2 = 0.f, a3 = 0.f;
        #pragma unroll
        for (int k = 0; k < BIT / 4; ++k) {
            float4 b  = uj[k];
            float4 c0 = s_ur[0][k], c1 = s_ur[1][k], c2 = s_ur[2][k], c3 = s_ur[3][k];
            a0 += c0.x * b.x + c0.y * b.y + c0.z * b.z + c0.w * b.w;
            a1 += c1.x * b.x + c1.y * b.y + c1.z * b.z + c1.w * b.w;
            a2 += c2.x * b.x + c2.y * b.y + c2.z * b.z + c2.w * b.w;
            a3 += c3.x * b.x + c3.y * b.y + c3.z * b.z + c3.w * b.w;
        }
        s_ip[0][j] = a0; s_ip[1][j] = a1; s_ip[2][j] = a2; s_ip[3][j] = a3;

        const float* yj = y + (size_t)j * NCLS;
        s_isneg[0][j] = (yj[lbl0] == 0.0f) ? 1 : 0;   // one-hot: exact 0/1
        s_isneg[1][j] = (yj[lbl1] == 0.0f) ? 1 : 0;
        s_isneg[2][j] = (yj[lbl2] == 0.0f) ? 1 : 0;
        s_isneg[3][j] = (yj[lbl3] == 0.0f) ? 1 : 0;
    }

    // --- loss2 partial: this block's RPB*BIT = 256 contiguous u elements ---
    {
        float v  = u[(size_t)r0 * BIT + tid];
        float sg = (v > 0.0f) ? 1.0f : ((v < 0.0f) ? -1.0f : 0.0f);
        float d  = v - sg;
        s_red[tid] = d * d;
    }
    __syncthreads();
    #pragma unroll
    for (int s = NT / 2; s > 0; s >>= 1) {
        if (tid < s) s_red[tid] += s_red[tid + s];
        __syncthreads();
    }
    if (tid == 0) g_loss2[blockIdx.x] = s_red[0];
    __syncthreads();

    // --- per-anchor-row triplet loss ---
    const int w    = tid >> 5;
    const int lane = tid & 31;

    #pragma unroll
    for (int i = 0; i < RPB; ++i) {
        // deterministic positive-index compaction via warp ballots
        unsigned m_lo = __ballot_sync(0xffffffffu, s_isneg[i][w * 64 + lane]      == 0);
        unsigned m_hi = __ballot_sync(0xffffffffu, s_isneg[i][w * 64 + 32 + lane] == 0);
        if (lane == 0)
            s_mask[w] = (unsigned long long)m_lo | ((unsigned long long)m_hi << 32);
        __syncthreads();

        if (tid == 0) {
            int c = 0;
            #pragma unroll
            for (int w2 = 0; w2 < 8; ++w2) {
                unsigned long long m = s_mask[w2];
                while (m) {
                    int b = __ffsll(m) - 1;
                    s_poslist[c++] = (short)(w2 * 64 + b);
                    m &= m - 1;
                }
            }
            s_npos = c;
        }
        __syncthreads();

        int   npos  = s_npos;
        int   total = npos * NN;
        float acc   = 0.0f;
        for (int idx = tid; idx < total; idx += NT) {
            int p = s_poslist[idx >> 9];   // idx / 512
            int n = idx & (NN - 1);        // idx % 512
            if (s_isneg[i][n]) {
                float t = s_ip[i][p] - s_ip[i][n] - ALPHA;
                t = fminf(fmaxf(t, -100.0f), 50.0f);
                // log1p(exp(t)) - t  ==  log1p(exp(-|t|)) + max(-t, 0)
                acc += log1pf(__expf(-fabsf(t))) + fmaxf(-t, 0.0f);
            }
        }

        s_red[tid] = acc;
        __syncthreads();
        #pragma unroll
        for (int s = NT / 2; s > 0; s >>= 1) {
            if (tid < s) s_red[tid] += s_red[tid + s];
            __syncthreads();
        }
        if (tid == 0) {
            int nneg = NN - npos;
            g_rowloss[r0 + i] = s_red[0] / fmaxf((float)(npos * nneg), 1.0f);
            g_valid[r0 + i]   = (npos > 0 && nneg > 0) ? 1 : 0;
        }
        __syncthreads();
    }
}

// ---------------------------------------------------------------------------
// Final kernel: deterministic reduction of 512 row losses + 128 loss2 partials.
// ---------------------------------------------------------------------------
__global__ void __launch_bounds__(512) final_kernel(float* __restrict__ out) {
    __shared__ float red1[512];
    __shared__ float red2[512];
    __shared__ int   redc[512];

    int tid = threadIdx.x;

    red1[tid] = g_valid[tid] ? g_rowloss[tid] : 0.0f;
    redc[tid] = g_valid[tid];
    red2[tid] = (tid < NB) ? g_loss2[tid] : 0.0f;
    __syncthreads();

    #pragma unroll
    for (int s = 256; s > 0; s >>= 1) {
        if (tid < s) {
            red1[tid] += red1[tid + s];
            red2[tid] += red2[tid + s];
            redc[tid] += redc[tid + s];
        }
        __syncthreads();
    }

    if (tid == 0) {
        float count = (float)redc[0];
        float loss1 = (count > 0.0f) ? (red1[0] / fmaxf(count, 1.0f)) : 0.0f;
        float loss2 = LAM * red2[0] / (float)(NN * BIT);
        out[0] = loss1 + loss2;
    }
}

// ---------------------------------------------------------------------------
extern "C" void kernel_launch(void* const* d_in, const int* in_sizes, int n_in,
                              void* d_out, int out_size) {
    const float* u;
    const float* y;
    if (in_sizes[0] == NN * BIT) {
        u = (const float*)d_in[0];
        y = (const float*)d_in[1];
    } else {
        u = (const float*)d_in[1];
        y = (const float*)d_in[0];
    }
    float* out = (float*)d_out;

    fused_kernel<<<NB, NT>>>(u, y);
    final_kernel<<<1, 512>>>(out);
}

// round 5
// speedup vs baseline: 2.2993x; 1.2423x over previous
#include <cuda_runtime.h>
#include <math.h>

#define NN    512
#define BIT   64
#define NCLS  100
#define ALPHA 5.0f
#define LAM   1.0f
#define RPB   4                 // rows per block
#define NB    (NN / RPB)        // 128 blocks
#define NT    256               // threads per block

// Scratch (allocation-free: __device__ globals)
__device__ float g_bsum[NB];     // per-block sum of valid row losses
__device__ float g_bcnt[NB];     // per-block count of valid rows
__device__ float g_bl2[NB];      // per-block loss2 partial (sum of d^2)
__device__ unsigned int g_done = 0;

// ---------------------------------------------------------------------------
// Single fused kernel. One block = 4 anchor rows; the 4 rows are processed by
// 4 independent 64-thread groups (2 warps each). Last block to finish performs
// the final deterministic reduction and writes the scalar output.
// ---------------------------------------------------------------------------
__global__ void __launch_bounds__(NT) fused_kernel(const float* __restrict__ u,
                                                   const float* __restrict__ y,
                                                   float* __restrict__ out) {
    __shared__ float4 s_ur[RPB][BIT / 4];          // anchor rows of u      (1 KB)
    __shared__ float  s_ip[RPB][NN];               // ip rows               (8 KB)
    __shared__ unsigned char s_isneg[RPB][NN];     // negative masks        (2 KB)
    __shared__ int    s_lbl[RPB];
    __shared__ unsigned s_gmask[RPB][16];          // pos bitmasks (16 x u32 / row)
    __shared__ short  s_poslist[RPB][NN];          // positive index lists  (4 KB)
    __shared__ int    s_npos[RPB];
    __shared__ float  s_part[8];                   // per-warp pair-loss partials
    __shared__ float  s_s2[8];                     // per-warp loss2 partials
    __shared__ int    s_islast;
    __shared__ float  r1[NB], r2[NB], r3[NB];      // final reduce scratch (1.5 KB)

    const int tid  = threadIdx.x;
    const int bid  = blockIdx.x;
    const int r0   = bid * RPB;
    const int lane = tid & 31;
    const int wrp  = tid >> 5;

    // --- phase 0: anchor rows of u into smem + label recovery (one-hot) ---
    if (tid < RPB * (BIT / 4)) {
        int i = tid >> 4;
        int k = tid & 15;
        s_ur[i][k] = ((const float4*)(u + (size_t)(r0 + i) * BIT))[k];
    }
    // exactly one (i,c) slot per row has y > 0.5 -> exactly one writer per s_lbl[i]
    for (int t = tid; t < RPB * NCLS; t += NT) {
        int i = t / NCLS;
        int c = t % NCLS;
        if (y[(size_t)(r0 + i) * NCLS + c] > 0.5f) s_lbl[i] = c;
    }
    __syncthreads();

    const int lbl0 = s_lbl[0], lbl1 = s_lbl[1], lbl2 = s_lbl[2], lbl3 = s_lbl[3];

    // --- phase 1: stream all 512 rows of u once; 4 dots each; isneg via y ---
    for (int j = tid; j < NN; j += NT) {
        const float4* __restrict__ uj = (const float4*)(u + (size_t)j * BIT);
        float a0 = 0.f, a1 = 0.f, a2 = 0.f, a3 = 0.f;
        #pragma unroll
        for (int k = 0; k < BIT / 4; ++k) {
            float4 b  = uj[k];
            float4 c0 = s_ur[0][k], c1 = s_ur[1][k], c2 = s_ur[2][k], c3 = s_ur[3][k];
            a0 += c0.x * b.x + c0.y * b.y + c0.z * b.z + c0.w * b.w;
            a1 += c1.x * b.x + c1.y * b.y + c1.z * b.z + c1.w * b.w;
            a2 += c2.x * b.x + c2.y * b.y + c2.z * b.z + c2.w * b.w;
            a3 += c3.x * b.x + c3.y * b.y + c3.z * b.z + c3.w * b.w;
        }
        s_ip[0][j] = a0; s_ip[1][j] = a1; s_ip[2][j] = a2; s_ip[3][j] = a3;

        const float* yj = y + (size_t)j * NCLS;
        s_isneg[0][j] = (yj[lbl0] == 0.0f) ? 1 : 0;   // one-hot: exact 0/1
        s_isneg[1][j] = (yj[lbl1] == 0.0f) ? 1 : 0;
        s_isneg[2][j] = (yj[lbl2] == 0.0f) ? 1 : 0;
        s_isneg[3][j] = (yj[lbl3] == 0.0f) ? 1 : 0;
    }

    // --- loss2 partial from smem copy of this block's 256 u values ---
    {
        float v  = ((const float*)s_ur)[tid];
        float sg = (v > 0.0f) ? 1.0f : ((v < 0.0f) ? -1.0f : 0.0f);
        float d  = v - sg;
        float s2 = d * d;
        #pragma unroll
        for (int o = 16; o > 0; o >>= 1) s2 += __shfl_xor_sync(0xffffffffu, s2, o);
        if (lane == 0) s_s2[wrp] = s2;
    }
    __syncthreads();

    // --- phase 2: per-row groups (g = tid>>6 handles row g; 64 threads) ---
    const int g  = tid >> 6;          // row within block
    const int gl = tid & 63;          // lane within group
    const int gw = (tid >> 5) & 1;    // warp half within group

    // positive bitmasks via ballots: each group warp covers 256 j's
    #pragma unroll
    for (int c = 0; c < 8; ++c) {
        unsigned m = __ballot_sync(0xffffffffu,
                                   s_isneg[g][gw * 256 + c * 32 + lane] == 0);
        if (lane == 0) s_gmask[g][gw * 8 + c] = m;
    }
    __syncthreads();

    // deterministic compaction by group leader (~npos ~ 5 pops)
    if (gl == 0) {
        int cnt = 0;
        #pragma unroll
        for (int c = 0; c < 16; ++c) {
            unsigned m = s_gmask[g][c];
            while (m) {
                int b = __ffs(m) - 1;
                s_poslist[g][cnt++] = (short)(c * 32 + b);
                m &= m - 1;
            }
        }
        s_npos[g] = cnt;
    }
    __syncthreads();

    // --- pair loop: (p in pos(g)) x (n in 0..511), n filtered by isneg ---
    const int npos  = s_npos[g];
    const int total = npos << 9;
    float acc = 0.0f;
    for (int idx = gl; idx < total; idx += 64) {
        int p = s_poslist[g][idx >> 9];
        int n = idx & (NN - 1);
        if (s_isneg[g][n]) {
            float t = s_ip[g][p] - s_ip[g][n] - ALPHA;
            t = fminf(fmaxf(t, -100.0f), 50.0f);
            // log1p(exp(t)) - t == log(1 + exp(-|t|)) + max(-t, 0)
            acc += __logf(1.0f + __expf(-fabsf(t))) + fmaxf(-t, 0.0f);
        }
    }
    #pragma unroll
    for (int o = 16; o > 0; o >>= 1) acc += __shfl_xor_sync(0xffffffffu, acc, o);
    if (lane == 0) s_part[wrp] = acc;
    __syncthreads();

    // --- block epilogue: combine 4 rows + loss2, publish, count arrival ---
    if (tid == 0) {
        float bsum = 0.0f, bcnt = 0.0f;
        #pragma unroll
        for (int gg = 0; gg < RPB; ++gg) {
            int   np = s_npos[gg];
            int   nn = NN - np;
            float rs = s_part[2 * gg] + s_part[2 * gg + 1];
            float rl = rs / fmaxf((float)(np * nn), 1.0f);
            if (np > 0 && nn > 0) { bsum += rl; bcnt += 1.0f; }
        }
        float bl2 = 0.0f;
        #pragma unroll
        for (int w2 = 0; w2 < 8; ++w2) bl2 += s_s2[w2];

        g_bsum[bid] = bsum;
        g_bcnt[bid] = bcnt;
        g_bl2[bid]  = bl2;
        __threadfence();
        unsigned prev = atomicAdd(&g_done, 1u);
        s_islast = (prev == NB - 1) ? 1 : 0;
    }
    __syncthreads();

    // --- last block performs the final deterministic reduction ---
    if (s_islast) {
        if (tid < NB) {
            r1[tid] = __ldcg(&g_bsum[tid]);
            r2[tid] = __ldcg(&g_bcnt[tid]);
            r3[tid] = __ldcg(&g_bl2[tid]);
        }
        __syncthreads();
        #pragma unroll
        for (int s = NB / 2; s > 0; s >>= 1) {
            if (tid < s) {
                r1[tid] += r1[tid + s];
                r2[tid] += r2[tid + s];
                r3[tid] += r3[tid + s];
            }
            __syncthreads();
        }
        if (tid == 0) {
            float count = r2[0];
            float loss1 = (count > 0.0f) ? (r1[0] / fmaxf(count, 1.0f)) : 0.0f;
            float loss2 = LAM * r3[0] / (float)(NN * BIT);
            out[0] = loss1 + loss2;
            g_done = 0;   // reset for next graph replay (safe: we are last)
        }
    }
}

// ---------------------------------------------------------------------------
extern "C" void kernel_launch(void* const* d_in, const int* in_sizes, int n_in,
                              void* d_out, int out_size) {
    const float* u;
    const float* y;
    if (in_sizes[0] == NN * BIT) {
        u = (const float*)d_in[0];
        y = (const float*)d_in[1];
    } else {
        u = (const float*)d_in[1];
        y = (const float*)d_in[0];
    }
    float* out = (float*)d_out;

    fused_kernel<<<NB, NT>>>(u, y, out);
}

// round 6
// speedup vs baseline: 2.4475x; 1.0645x over previous
#include <cuda_runtime.h>
#include <math.h>

#define NN    512
#define BIT   64
#define NCLS  100
#define ALPHA 5.0f
#define LAM   1.0f
#define RPB   4                 // rows per block
#define NB    (NN / RPB)        // 128 blocks
#define NT    256               // threads per block

// Scratch (allocation-free: __device__ globals)
__device__ float g_bsum[NB];     // per-block sum of valid row losses
__device__ float g_bcnt[NB];     // per-block count of valid rows
__device__ float g_bl2[NB];      // per-block loss2 partial (sum of d^2)
__device__ unsigned int g_done = 0;

// ---------------------------------------------------------------------------
// Single fused kernel. One block = 4 anchor rows; 4 independent 64-thread
// groups handle the 4 rows' pair loops. Last block reduces + writes output.
// __launch_bounds__(NT, 2) caps regs at 128 (R5 hit the 255-reg ceiling).
// ---------------------------------------------------------------------------
__global__ void __launch_bounds__(NT, 2) fused_kernel(const float* __restrict__ u,
                                                      const float* __restrict__ y,
                                                      float* __restrict__ out) {
    __shared__ float4 s_ur[RPB][BIT / 4];          // anchor rows of u      (1 KB)
    __shared__ float  s_ip[RPB][NN];               // ip rows               (8 KB)
    __shared__ unsigned char s_isneg[RPB][NN];     // negative masks        (2 KB)
    __shared__ int    s_lbl[RPB];
    __shared__ unsigned s_gmask[RPB][16];          // pos bitmasks (16 x u32 / row)
    __shared__ short  s_poslist[RPB][NN];          // positive index lists  (4 KB)
    __shared__ int    s_npos[RPB];
    __shared__ float  s_part[8];                   // per-warp pair-loss partials
    __shared__ float  s_s2[8];                     // per-warp loss2 partials
    __shared__ int    s_islast;
    __shared__ float  r1[NB], r2[NB], r3[NB];      // final reduce scratch (1.5 KB)

    const int tid  = threadIdx.x;
    const int bid  = blockIdx.x;
    const int r0   = bid * RPB;
    const int lane = tid & 31;
    const int wrp  = tid >> 5;

    // --- phase 0: anchor rows of u into smem + label recovery (one-hot) ---
    if (tid < RPB * (BIT / 4)) {
        int i = tid >> 4;
        int k = tid & 15;
        s_ur[i][k] = ((const float4*)(u + (size_t)(r0 + i) * BIT))[k];
    }
    // exactly one (i,c) slot per row has y > 0.5 -> exactly one writer per s_lbl[i]
    for (int t = tid; t < RPB * NCLS; t += NT) {
        int i = t / NCLS;
        int c = t % NCLS;
        if (y[(size_t)(r0 + i) * NCLS + c] > 0.5f) s_lbl[i] = c;
    }
    __syncthreads();

    // --- phase 1a: dot products. Each thread handles j and j+256 in one pass
    // so the anchor-row smem loads (c0..c3) are used twice per k step. ---
    {
        const int j1 = tid;
        const int j2 = tid + NT;
        const float4* __restrict__ uj1 = (const float4*)(u + (size_t)j1 * BIT);
        const float4* __restrict__ uj2 = (const float4*)(u + (size_t)j2 * BIT);
        float a00 = 0.f, a01 = 0.f, a02 = 0.f, a03 = 0.f;
        float a10 = 0.f, a11 = 0.f, a12 = 0.f, a13 = 0.f;
        #pragma unroll
        for (int k = 0; k < BIT / 4; ++k) {
            float4 b1 = uj1[k];
            float4 b2 = uj2[k];
            float4 c0 = s_ur[0][k];
            float4 c1 = s_ur[1][k];
            float4 c2 = s_ur[2][k];
            float4 c3 = s_ur[3][k];
            a00 += c0.x * b1.x + c0.y * b1.y + c0.z * b1.z + c0.w * b1.w;
            a01 += c1.x * b1.x + c1.y * b1.y + c1.z * b1.z + c1.w * b1.w;
            a02 += c2.x * b1.x + c2.y * b1.y + c2.z * b1.z + c2.w * b1.w;
            a03 += c3.x * b1.x + c3.y * b1.y + c3.z * b1.z + c3.w * b1.w;
            a10 += c0.x * b2.x + c0.y * b2.y + c0.z * b2.z + c0.w * b2.w;
            a11 += c1.x * b2.x + c1.y * b2.y + c1.z * b2.z + c1.w * b2.w;
            a12 += c2.x * b2.x + c2.y * b2.y + c2.z * b2.z + c2.w * b2.w;
            a13 += c3.x * b2.x + c3.y * b2.y + c3.z * b2.z + c3.w * b2.w;
        }
        s_ip[0][j1] = a00; s_ip[1][j1] = a01; s_ip[2][j1] = a02; s_ip[3][j1] = a03;
        s_ip[0][j2] = a10; s_ip[1][j2] = a11; s_ip[2][j2] = a12; s_ip[3][j2] = a13;
    }

    // --- phase 1b: isneg masks via one-hot column reads (labels needed) ---
    {
        const int lbl0 = s_lbl[0], lbl1 = s_lbl[1], lbl2 = s_lbl[2], lbl3 = s_lbl[3];
        #pragma unroll
        for (int rep = 0; rep < 2; ++rep) {
            int j = tid + rep * NT;
            const float* yj = y + (size_t)j * NCLS;
            s_isneg[0][j] = (yj[lbl0] == 0.0f) ? 1 : 0;   // one-hot: exact 0/1
            s_isneg[1][j] = (yj[lbl1] == 0.0f) ? 1 : 0;
            s_isneg[2][j] = (yj[lbl2] == 0.0f) ? 1 : 0;
            s_isneg[3][j] = (yj[lbl3] == 0.0f) ? 1 : 0;
        }
    }

    // --- loss2 partial from smem copy of this block's 256 u values ---
    {
        float v  = ((const float*)s_ur)[tid];
        float sg = (v > 0.0f) ? 1.0f : ((v < 0.0f) ? -1.0f : 0.0f);
        float d  = v - sg;
        float s2 = d * d;
        #pragma unroll
        for (int o = 16; o > 0; o >>= 1) s2 += __shfl_xor_sync(0xffffffffu, s2, o);
        if (lane == 0) s_s2[wrp] = s2;
    }
    __syncthreads();

    // --- phase 2: per-row groups (g = tid>>6 handles row g; 64 threads) ---
    const int g  = tid >> 6;          // row within block
    const int gl = tid & 63;          // lane within group
    const int gw = (tid >> 5) & 1;    // warp half within group

    // positive bitmasks via ballots: each group warp covers 256 j's
    #pragma unroll
    for (int c = 0; c < 8; ++c) {
        unsigned m = __ballot_sync(0xffffffffu,
                                   s_isneg[g][gw * 256 + c * 32 + lane] == 0);
        if (lane == 0) s_gmask[g][gw * 8 + c] = m;
    }
    __syncthreads();

    // deterministic compaction by group leader (~npos ~ 5 pops)
    if (gl == 0) {
        int cnt = 0;
        #pragma unroll
        for (int c = 0; c < 16; ++c) {
            unsigned m = s_gmask[g][c];
            while (m) {
                int b = __ffs(m) - 1;
                s_poslist[g][cnt++] = (short)(c * 32 + b);
                m &= m - 1;
            }
        }
        s_npos[g] = cnt;
    }
    __syncthreads();

    // --- pair loop: (p in pos(g)) x (n in 0..511), n filtered by isneg ---
    const int npos  = s_npos[g];
    const int total = npos << 9;
    float acc = 0.0f;
    for (int idx = gl; idx < total; idx += 64) {
        int p = s_poslist[g][idx >> 9];
        int n = idx & (NN - 1);
        if (s_isneg[g][n]) {
            float t = s_ip[g][p] - s_ip[g][n] - ALPHA;
            t = fminf(fmaxf(t, -100.0f), 50.0f);
            // log1p(exp(t)) - t == log(1 + exp(-|t|)) + max(-t, 0)
            acc += __logf(1.0f + __expf(-fabsf(t))) + fmaxf(-t, 0.0f);
        }
    }
    #pragma unroll
    for (int o = 16; o > 0; o >>= 1) acc += __shfl_xor_sync(0xffffffffu, acc, o);
    if (lane == 0) s_part[wrp] = acc;
    __syncthreads();

    // --- block epilogue: combine 4 rows + loss2, publish, count arrival ---
    if (tid == 0) {
        float bsum = 0.0f, bcnt = 0.0f;
        #pragma unroll
        for (int gg = 0; gg < RPB; ++gg) {
            int   np = s_npos[gg];
            int   nn = NN - np;
            float rs = s_part[2 * gg] + s_part[2 * gg + 1];
            float rl = rs / fmaxf((float)(np * nn), 1.0f);
            if (np > 0 && nn > 0) { bsum += rl; bcnt += 1.0f; }
        }
        float bl2 = 0.0f;
        #pragma unroll
        for (int w2 = 0; w2 < 8; ++w2) bl2 += s_s2[w2];

        g_bsum[bid] = bsum;
        g_bcnt[bid] = bcnt;
        g_bl2[bid]  = bl2;
        __threadfence();
        unsigned prev = atomicAdd(&g_done, 1u);
        s_islast = (prev == NB - 1) ? 1 : 0;
    }
    __syncthreads();

    // --- last block performs the final deterministic reduction ---
    if (s_islast) {
        if (tid < NB) {
            r1[tid] = __ldcg(&g_bsum[tid]);
            r2[tid] = __ldcg(&g_bcnt[tid]);
            r3[tid] = __ldcg(&g_bl2[tid]);
        }
        __syncthreads();
        #pragma unroll
        for (int s = NB / 2; s > 0; s >>= 1) {
            if (tid < s) {
                r1[tid] += r1[tid + s];
                r2[tid] += r2[tid + s];
                r3[tid] += r3[tid + s];
            }
            __syncthreads();
        }
        if (tid == 0) {
            float count = r2[0];
            float loss1 = (count > 0.0f) ? (r1[0] / fmaxf(count, 1.0f)) : 0.0f;
            float loss2 = LAM * r3[0] / (float)(NN * BIT);
            out[0] = loss1 + loss2;
            g_done = 0;   // reset for next graph replay (safe: we are last)
        }
    }
}

// ---------------------------------------------------------------------------
extern "C" void kernel_launch(void* const* d_in, const int* in_sizes, int n_in,
                              void* d_out, int out_size) {
    const float* u;
    const float* y;
    if (in_sizes[0] == NN * BIT) {
        u = (const float*)d_in[0];
        y = (const float*)d_in[1];
    } else {
        u = (const float*)d_in[1];
        y = (const float*)d_in[0];
    }
    float* out = (float*)d_out;

    fused_kernel<<<NB, NT>>>(u, y, out);
}

// round 7
// speedup vs baseline: 2.6630x; 1.0880x over previous
#include <cuda_runtime.h>
#include <math.h>

#define NN    512
#define BIT   64
#define NCLS  100
#define ALPHA 5.0f
#define LAM   1.0f
#define RPB   2                 // rows per block
#define NB    (NN / RPB)        // 256 blocks
#define NT    256               // threads per block

// Scratch (allocation-free: __device__ globals)
__device__ float g_bsum[NB];     // per-block sum of valid row losses
__device__ float g_bcnt[NB];     // per-block count of valid rows
__device__ float g_bl2[NB];      // per-block loss2 partial (sum of d^2)
__device__ unsigned int g_done = 0;

// ---------------------------------------------------------------------------
// Single fused kernel. One block = 2 anchor rows; 2 independent 128-thread
// groups handle the 2 rows' pair loops. 256 blocks -> 2 blocks/SM (occ 25%).
// Last block to finish reduces the per-block partials and writes the output.
// ---------------------------------------------------------------------------
__global__ void __launch_bounds__(NT, 2) fused_kernel(const float* __restrict__ u,
                                                      const float* __restrict__ y,
                                                      float* __restrict__ out) {
    __shared__ float4 s_ur[RPB][BIT / 4];          // anchor rows of u     (0.5 KB)
    __shared__ float  s_ip[RPB][NN];               // ip rows              (4 KB)
    __shared__ unsigned char s_isneg[RPB][NN];     // negative masks       (1 KB)
    __shared__ int    s_lbl[RPB];
    __shared__ unsigned s_gmask[RPB][16];          // pos bitmasks (16 u32 / row)
    __shared__ short  s_poslist[RPB][NN];          // positive index lists (2 KB)
    __shared__ int    s_npos[RPB];
    __shared__ float  s_part[8];                   // per-warp pair-loss partials
    __shared__ float  s_s2[8];                     // per-warp loss2 partials
    __shared__ int    s_islast;
    __shared__ float  r1[NB], r2[NB], r3[NB];      // final reduce scratch (3 KB)

    const int tid  = threadIdx.x;
    const int bid  = blockIdx.x;
    const int r0   = bid * RPB;
    const int lane = tid & 31;
    const int wrp  = tid >> 5;

    // --- phase 0: anchor rows of u into smem + label recovery (one-hot) ---
    if (tid < RPB * (BIT / 4)) {          // 32 float4 loads
        int i = tid >> 4;
        int k = tid & 15;
        s_ur[i][k] = ((const float4*)(u + (size_t)(r0 + i) * BIT))[k];
    }
    // exactly one (i,c) slot per row has y > 0.5 -> exactly one writer per s_lbl[i]
    if (tid < RPB * NCLS) {               // 200 <= 256 threads
        int i = tid / NCLS;
        int c = tid % NCLS;
        if (y[(size_t)(r0 + i) * NCLS + c] > 0.5f) s_lbl[i] = c;
    }
    __syncthreads();

    // --- phase 1a: dot products; each thread handles j and j+256 ---
    {
        const int j1 = tid;
        const int j2 = tid + NT;
        const float4* __restrict__ uj1 = (const float4*)(u + (size_t)j1 * BIT);
        const float4* __restrict__ uj2 = (const float4*)(u + (size_t)j2 * BIT);
        float a00 = 0.f, a01 = 0.f, a10 = 0.f, a11 = 0.f;
        #pragma unroll
        for (int k = 0; k < BIT / 4; ++k) {
            float4 b1 = uj1[k];
            float4 b2 = uj2[k];
            float4 c0 = s_ur[0][k];
            float4 c1 = s_ur[1][k];
            a00 += c0.x * b1.x + c0.y * b1.y + c0.z * b1.z + c0.w * b1.w;
            a01 += c1.x * b1.x + c1.y * b1.y + c1.z * b1.z + c1.w * b1.w;
            a10 += c0.x * b2.x + c0.y * b2.y + c0.z * b2.z + c0.w * b2.w;
            a11 += c1.x * b2.x + c1.y * b2.y + c1.z * b2.z + c1.w * b2.w;
        }
        s_ip[0][j1] = a00; s_ip[1][j1] = a01;
        s_ip[0][j2] = a10; s_ip[1][j2] = a11;
    }

    // --- phase 1b: isneg masks via one-hot column reads ---
    {
        const int lbl0 = s_lbl[0], lbl1 = s_lbl[1];
        #pragma unroll
        for (int rep = 0; rep < 2; ++rep) {
            int j = tid + rep * NT;
            const float* yj = y + (size_t)j * NCLS;
            s_isneg[0][j] = (yj[lbl0] == 0.0f) ? 1 : 0;   // one-hot: exact 0/1
            s_isneg[1][j] = (yj[lbl1] == 0.0f) ? 1 : 0;
        }
    }

    // --- loss2 partial: this block's RPB*BIT = 128 u values (from smem) ---
    {
        float v  = (tid < RPB * BIT) ? ((const float*)s_ur)[tid] : 0.0f;
        float sg = (v > 0.0f) ? 1.0f : ((v < 0.0f) ? -1.0f : 0.0f);
        float d  = v - sg;
        float s2 = d * d;
        #pragma unroll
        for (int o = 16; o > 0; o >>= 1) s2 += __shfl_xor_sync(0xffffffffu, s2, o);
        if (lane == 0) s_s2[wrp] = s2;
    }
    __syncthreads();

    // --- phase 2: per-row groups (g = tid>>7 handles row g; 128 threads) ---
    const int g  = tid >> 7;          // row within block (0/1)
    const int gl = tid & 127;         // lane within group
    const int gw = (tid >> 5) & 3;    // warp within group (0..3)

    // positive bitmasks via ballots: each group warp covers 128 j's
    #pragma unroll
    for (int c = 0; c < 4; ++c) {
        unsigned m = __ballot_sync(0xffffffffu,
                                   s_isneg[g][gw * 128 + c * 32 + lane] == 0);
        if (lane == 0) s_gmask[g][gw * 4 + c] = m;
    }
    __syncthreads();

    // deterministic compaction by group leader (~npos ~ 5 pops)
    if (gl == 0) {
        int cnt = 0;
        #pragma unroll
        for (int c = 0; c < 16; ++c) {
            unsigned m = s_gmask[g][c];
            while (m) {
                int b = __ffs(m) - 1;
                s_poslist[g][cnt++] = (short)(c * 32 + b);
                m &= m - 1;
            }
        }
        s_npos[g] = cnt;
    }
    __syncthreads();

    // --- pair loop: (p in pos(g)) x (n in 0..511), n filtered by isneg ---
    const int npos  = s_npos[g];
    const int total = npos << 9;
    float acc = 0.0f;
    for (int idx = gl; idx < total; idx += 128) {
        int p = s_poslist[g][idx >> 9];
        int n = idx & (NN - 1);
        if (s_isneg[g][n]) {
            float t = s_ip[g][p] - s_ip[g][n] - ALPHA;
            t = fminf(fmaxf(t, -100.0f), 50.0f);
            // log1p(exp(t)) - t == log(1 + exp(-|t|)) + max(-t, 0)
            acc += __logf(1.0f + __expf(-fabsf(t))) + fmaxf(-t, 0.0f);
        }
    }
    #pragma unroll
    for (int o = 16; o > 0; o >>= 1) acc += __shfl_xor_sync(0xffffffffu, acc, o);
    if (lane == 0) s_part[wrp] = acc;
    __syncthreads();

    // --- block epilogue: combine 2 rows + loss2, publish, count arrival ---
    if (tid == 0) {
        float bsum = 0.0f, bcnt = 0.0f;
        #pragma unroll
        for (int gg = 0; gg < RPB; ++gg) {
            int   np = s_npos[gg];
            int   nn = NN - np;
            float rs = s_part[4 * gg] + s_part[4 * gg + 1]
                     + s_part[4 * gg + 2] + s_part[4 * gg + 3];
            float rl = rs / fmaxf((float)(np * nn), 1.0f);
            if (np > 0 && nn > 0) { bsum += rl; bcnt += 1.0f; }
        }
        float bl2 = 0.0f;
        #pragma unroll
        for (int w2 = 0; w2 < 8; ++w2) bl2 += s_s2[w2];

        g_bsum[bid] = bsum;
        g_bcnt[bid] = bcnt;
        g_bl2[bid]  = bl2;
        __threadfence();
        unsigned prev = atomicAdd(&g_done, 1u);
        s_islast = (prev == NB - 1) ? 1 : 0;
    }
    __syncthreads();

    // --- last block performs the final deterministic reduction ---
    if (s_islast) {
        if (tid < NB) {
            r1[tid] = __ldcg(&g_bsum[tid]);
            r2[tid] = __ldcg(&g_bcnt[tid]);
            r3[tid] = __ldcg(&g_bl2[tid]);
        }
        __syncthreads();
        #pragma unroll
        for (int s = NB / 2; s > 0; s >>= 1) {
            if (tid < s) {
                r1[tid] += r1[tid + s];
                r2[tid] += r2[tid + s];
                r3[tid] += r3[tid + s];
            }
            __syncthreads();
        }
        if (tid == 0) {
            float count = r2[0];
            float loss1 = (count > 0.0f) ? (r1[0] / fmaxf(count, 1.0f)) : 0.0f;
            float loss2 = LAM * r3[0] / (float)(NN * BIT);
            out[0] = loss1 + loss2;
            g_done = 0;   // reset for next graph replay (safe: we are last)
        }
    }
}

// ---------------------------------------------------------------------------
extern "C" void kernel_launch(void* const* d_in, const int* in_sizes, int n_in,
                              void* d_out, int out_size) {
    const float* u;
    const float* y;
    if (in_sizes[0] == NN * BIT) {
        u = (const float*)d_in[0];
        y = (const float*)d_in[1];
    } else {
        u = (const float*)d_in[1];
        y = (const float*)d_in[0];
    }
    float* out = (float*)d_out;

    fused_kernel<<<NB, NT>>>(u, y, out);
}

// round 8
// speedup vs baseline: 2.6889x; 1.0097x over previous
#include <cuda_runtime.h>
#include <math.h>

#define NN    512
#define BIT   64
#define NCLS  100
#define ALPHA 5.0f
#define LAM   1.0f
#define RPB   2                 // rows per block
#define NB    (NN / RPB)        // 256 blocks
#define NT    256               // threads per block

// Scratch (allocation-free: __device__ globals)
__device__ float4 g_part[NB];    // {bsum, bcnt, bl2, unused} per block
__device__ unsigned int g_done = 0;

// ---------------------------------------------------------------------------
// Single fused kernel. One block = 2 anchor rows; 2 independent 128-thread
// groups handle the 2 rows' pair loops. Last block reduces + writes output.
// Key R8 changes: bounded unroll (no spills), early scattered gathers,
// register-sourced ballots (one fewer sync), float4 partials.
// ---------------------------------------------------------------------------
__global__ void __launch_bounds__(NT, 2) fused_kernel(const float* __restrict__ u,
                                                      const float* __restrict__ y,
                                                      float* __restrict__ out) {
    __shared__ float4 s_ur[RPB][BIT / 4];          // anchor rows of u     (0.5 KB)
    __shared__ float  s_ip[RPB][NN];               // ip rows              (4 KB)
    __shared__ unsigned char s_isneg[RPB][NN];     // negative masks       (1 KB)
    __shared__ int    s_lbl[RPB];
    __shared__ unsigned s_gmask[RPB][16];          // pos bitmasks (16 u32 / row)
    __shared__ short  s_poslist[RPB][NN];          // positive index lists (2 KB)
    __shared__ int    s_npos[RPB];
    __shared__ float  s_part[8];                   // per-warp pair-loss partials
    __shared__ float  s_s2[8];                     // per-warp loss2 partials
    __shared__ int    s_islast;
    __shared__ float4 s_rf[NB];                    // final reduce scratch (4 KB)

    const int tid  = threadIdx.x;
    const int bid  = blockIdx.x;
    const int r0   = bid * RPB;
    const int lane = tid & 31;
    const int wrp  = tid >> 5;

    // --- phase 0: anchor rows of u into smem + label recovery (one-hot) ---
    if (tid < RPB * (BIT / 4)) {          // 32 float4 loads
        int i = tid >> 4;
        int k = tid & 15;
        s_ur[i][k] = ((const float4*)(u + (size_t)(r0 + i) * BIT))[k];
    }
    if (tid < RPB * NCLS) {               // 200 <= 256 threads; one writer/row
        int i = tid / NCLS;
        int c = tid % NCLS;
        if (y[(size_t)(r0 + i) * NCLS + c] > 0.5f) s_lbl[i] = c;
    }
    __syncthreads();

    const int j1 = tid;
    const int j2 = tid + NT;
    const int lbl0 = s_lbl[0], lbl1 = s_lbl[1];

    // --- issue scattered isneg gathers EARLY; latency hides under dot loop ---
    const float yv00 = __ldg(y + (size_t)j1 * NCLS + lbl0);
    const float yv01 = __ldg(y + (size_t)j1 * NCLS + lbl1);
    const float yv10 = __ldg(y + (size_t)j2 * NCLS + lbl0);
    const float yv11 = __ldg(y + (size_t)j2 * NCLS + lbl1);

    // --- dot products; bounded unroll to avoid register spills ---
    {
        const float4* __restrict__ uj1 = (const float4*)(u + (size_t)j1 * BIT);
        const float4* __restrict__ uj2 = (const float4*)(u + (size_t)j2 * BIT);
        float a00 = 0.f, a01 = 0.f, a10 = 0.f, a11 = 0.f;
        #pragma unroll 4
        for (int k = 0; k < BIT / 4; ++k) {
            float4 b1 = uj1[k];
            float4 b2 = uj2[k];
            float4 c0 = s_ur[0][k];
            float4 c1 = s_ur[1][k];
            a00 += c0.x * b1.x + c0.y * b1.y + c0.z * b1.z + c0.w * b1.w;
            a01 += c1.x * b1.x + c1.y * b1.y + c1.z * b1.z + c1.w * b1.w;
            a10 += c0.x * b2.x + c0.y * b2.y + c0.z * b2.z + c0.w * b2.w;
            a11 += c1.x * b2.x + c1.y * b2.y + c1.z * b2.z + c1.w * b2.w;
        }
        s_ip[0][j1] = a00; s_ip[1][j1] = a01;
        s_ip[0][j2] = a10; s_ip[1][j2] = a11;
    }

    // --- isneg from the prefetched register values (one-hot: exact 0/1) ---
    const unsigned char n00 = (yv00 == 0.0f) ? 1 : 0;
    const unsigned char n01 = (yv01 == 0.0f) ? 1 : 0;
    const unsigned char n10 = (yv10 == 0.0f) ? 1 : 0;
    const unsigned char n11 = (yv11 == 0.0f) ? 1 : 0;
    s_isneg[0][j1] = n00;  s_isneg[1][j1] = n01;
    s_isneg[0][j2] = n10;  s_isneg[1][j2] = n11;

    // --- ballots straight from registers: warp w owns j = w*32+lane (+256) ---
    {
        unsigned m;
        m = __ballot_sync(0xffffffffu, n00 == 0);
        if (lane == 0) s_gmask[0][wrp] = m;
        m = __ballot_sync(0xffffffffu, n01 == 0);
        if (lane == 0) s_gmask[1][wrp] = m;
        m = __ballot_sync(0xffffffffu, n10 == 0);
        if (lane == 0) s_gmask[0][wrp + 8] = m;
        m = __ballot_sync(0xffffffffu, n11 == 0);
        if (lane == 0) s_gmask[1][wrp + 8] = m;
    }

    // --- loss2 partial: this block's RPB*BIT = 128 u values (from smem) ---
    {
        float v  = (tid < RPB * BIT) ? ((const float*)s_ur)[tid] : 0.0f;
        float sg = (v > 0.0f) ? 1.0f : ((v < 0.0f) ? -1.0f : 0.0f);
        float d  = v - sg;
        float s2 = d * d;
        #pragma unroll
        for (int o = 16; o > 0; o >>= 1) s2 += __shfl_xor_sync(0xffffffffu, s2, o);
        if (lane == 0) s_s2[wrp] = s2;
    }
    __syncthreads();

    // --- per-row groups (g = tid>>7 handles row g; 128 threads each) ---
    const int g  = tid >> 7;          // row within block (0/1)
    const int gl = tid & 127;         // lane within group

    // deterministic compaction by group leader (~npos ~ 5 pops)
    if (gl == 0) {
        int cnt = 0;
        #pragma unroll
        for (int c = 0; c < 16; ++c) {
            unsigned m = s_gmask[g][c];
            while (m) {
                int b = __ffs(m) - 1;
                s_poslist[g][cnt++] = (short)(c * 32 + b);
                m &= m - 1;
            }
        }
        s_npos[g] = cnt;
    }
    __syncthreads();

    // --- pair loop: (p in pos(g)) x (n in 0..511), n filtered by isneg ---
    const int npos  = s_npos[g];
    const int total = npos << 9;
    float acc = 0.0f;
    for (int idx = gl; idx < total; idx += 128) {
        int p = s_poslist[g][idx >> 9];
        int n = idx & (NN - 1);
        if (s_isneg[g][n]) {
            float t = s_ip[g][p] - s_ip[g][n] - ALPHA;
            t = fminf(fmaxf(t, -100.0f), 50.0f);
            // log1p(exp(t)) - t == log(1 + exp(-|t|)) + max(-t, 0)
            acc += __logf(1.0f + __expf(-fabsf(t))) + fmaxf(-t, 0.0f);
        }
    }
    #pragma unroll
    for (int o = 16; o > 0; o >>= 1) acc += __shfl_xor_sync(0xffffffffu, acc, o);
    if (lane == 0) s_part[wrp] = acc;
    __syncthreads();

    // --- block epilogue: combine 2 rows + loss2, publish, count arrival ---
    if (tid == 0) {
        float bsum = 0.0f, bcnt = 0.0f;
        #pragma unroll
        for (int gg = 0; gg < RPB; ++gg) {
            int   np = s_npos[gg];
            int   nn = NN - np;
            float rs = s_part[4 * gg] + s_part[4 * gg + 1]
                     + s_part[4 * gg + 2] + s_part[4 * gg + 3];
            float rl = rs / fmaxf((float)(np * nn), 1.0f);
            if (np > 0 && nn > 0) { bsum += rl; bcnt += 1.0f; }
        }
        float bl2 = 0.0f;
        #pragma unroll
        for (int w2 = 0; w2 < 8; ++w2) bl2 += s_s2[w2];

        g_part[bid] = make_float4(bsum, bcnt, bl2, 0.0f);
        __threadfence();
        unsigned prev = atomicAdd(&g_done, 1u);
        s_islast = (prev == NB - 1) ? 1 : 0;
    }
    __syncthreads();

    // --- last block performs the final deterministic reduction ---
    if (s_islast) {
        s_rf[tid] = __ldcg(&g_part[tid]);   // tid < NB == NT
        __syncthreads();
        #pragma unroll
        for (int s = NB / 2; s > 0; s >>= 1) {
            if (tid < s) {
                float4 a = s_rf[tid];
                float4 b = s_rf[tid + s];
                s_rf[tid] = make_float4(a.x + b.x, a.y + b.y, a.z + b.z, 0.0f);
            }
            __syncthreads();
        }
        if (tid == 0) {
            float4 r = s_rf[0];
            float count = r.y;
            float loss1 = (count > 0.0f) ? (r.x / fmaxf(count, 1.0f)) : 0.0f;
            float loss2 = LAM * r.z / (float)(NN * BIT);
            out[0] = loss1 + loss2;
            g_done = 0;   // reset for next graph replay (safe: we are last)
        }
    }
}

// ---------------------------------------------------------------------------
extern "C" void kernel_launch(void* const* d_in, const int* in_sizes, int n_in,
                              void* d_out, int out_size) {
    const float* u;
    const float* y;
    if (in_sizes[0] == NN * BIT) {
        u = (const float*)d_in[0];
        y = (const float*)d_in[1];
    } else {
        u = (const float*)d_in[1];
        y = (const float*)d_in[0];
    }
    float* out = (float*)d_out;

    fused_kernel<<<NB, NT>>>(u, y, out);
}